// round 9
// baseline (speedup 1.0000x reference)
#include <cuda_runtime.h>
#include <cuda_bf16.h>
#include <math.h>

#define NN   50000
#define EE   400000
#define INC  256
#define HID  128
#define H4   512
#define FCH  64
#define OUTC 2
#define GCAP 256   // smem exp cache per head in gat_fused
#define NB   ((NN + 255) / 256)   // scan tiles = 196

// ---------------- scratch (device globals; no allocation allowed) ----------------
__device__ float g_yC  [NN * 256];   // [lin_l | lin_r] concat, SAGE1
__device__ float g_pre1[NN * HID];
__device__ float g_xh  [NN * H4];
__device__ float g_asrc[NN * 4];
__device__ float g_adst[NN * 4];
__device__ float g_pre2[NN * H4];
__device__ float g_y2C [NN * 256];   // [lin_l | lin_r] concat, SAGE2
__device__ float g_pre3[NN * HID];
__device__ float g_f1p [NN * FCH];
__device__ float g_stats[1024];      // [0:512) sum, [512:1024) sumsq
__device__ float g_scsh[2048];       // sc1@0 sh1@128 sc2@256 sh2@768 sc3@1280 sh3@1408 sc4@1536 sh4@1600
__device__ float g_wcat1[256 * INC];
__device__ float g_wcat2[256 * H4];
__device__ float g_va  [HID * 8];    // low-rank attn: [k][2h]=Wg^T a_s, [k][2h+1]=Wg^T a_d
__device__ int   g_rowptr[NN + 1];
__device__ int   g_cnt [NN];
__device__ int   g_cnt2[NN];
__device__ int   g_bsum[NB];
__device__ int   g_boff[NB];
__device__ int   g_csrc[EE];         // CSR: src node per slot, grouped by dst

// ---------------- generic fill ----------------
__global__ void fillk(float* p, float v, long n) {
    long i = (long)blockIdx.x * blockDim.x + threadIdx.x;
    long stride = (long)gridDim.x * blockDim.x;
    for (; i < n; i += stride) p[i] = v;
}

// ---------------- CSR build ----------------
__global__ void count_kernel(const int* __restrict__ dst, int* cnt, int E) {
    int e = blockIdx.x * blockDim.x + threadIdx.x;
    if (e < E) atomicAdd(&cnt[dst[e]], 1);
}

__global__ void scan_part(const int* __restrict__ cnt, int* bsum) {
    __shared__ int s[256];
    int t = threadIdx.x;
    int i = blockIdx.x * 256 + t;
    int v = (i < NN) ? cnt[i] : 0;
    s[t] = v;
    __syncthreads();
    for (int off = 128; off; off >>= 1) {
        if (t < off) s[t] += s[t + off];
        __syncthreads();
    }
    if (t == 0) bsum[blockIdx.x] = s[0];
}

__global__ void scan_tops(const int* __restrict__ bsum, int* boff, int* rowptr) {
    __shared__ int s[256];
    int t = threadIdx.x;
    int v = (t < NB) ? bsum[t] : 0;
    s[t] = v;
    __syncthreads();
#pragma unroll
    for (int off = 1; off < 256; off <<= 1) {
        int u = (t >= off) ? s[t - off] : 0;
        __syncthreads();
        s[t] += u;
        __syncthreads();
    }
    if (t < NB) boff[t] = s[t] - v;
    if (t == 255) rowptr[NN] = s[255];
}

__global__ void scan_expand(const int* __restrict__ cnt, const int* __restrict__ boff,
                            int* rowptr) {
    __shared__ int s[256];
    int t = threadIdx.x;
    int i = blockIdx.x * 256 + t;
    int v = (i < NN) ? cnt[i] : 0;
    s[t] = v;
    __syncthreads();
#pragma unroll
    for (int off = 1; off < 256; off <<= 1) {
        int u = (t >= off) ? s[t - off] : 0;
        __syncthreads();
        s[t] += u;
        __syncthreads();
    }
    if (i < NN) rowptr[i] = boff[blockIdx.x] + s[t] - v;
}

__global__ void scatter_kernel(const int* __restrict__ src, const int* __restrict__ dst,
                               const int* __restrict__ rowptr, int* cnt2, int* csrc, int E) {
    int e = blockIdx.x * blockDim.x + threadIdx.x;
    if (e >= E) return;
    int d = dst[e];
    int pos = rowptr[d] + atomicAdd(&cnt2[d], 1);
    csrc[pos] = src[e];
}

// =====================================================================
// Tensor-core GEMM: C[m,n] = sum_k A'[m,k] * W[n,k]   (tf32 HMMA)
// BN=true: A'[m,k] = elu(A[m,k]*sc[k] + sh[k]) applied in the load path.
// =====================================================================
#define SMP 20

#define CVT_TF32(u, f) asm("cvt.rna.tf32.f32 %0, %1;" : "=r"(u) : "f"(f))

#define MMA_TF32(c, a, b) \
    asm volatile("mma.sync.aligned.m16n8k8.row.col.f32.tf32.tf32.f32 " \
                 "{%0,%1,%2,%3}, {%4,%5,%6,%7}, {%8,%9}, {%0,%1,%2,%3};" \
                 : "+f"(c[0]), "+f"(c[1]), "+f"(c[2]), "+f"(c[3]) \
                 : "r"(a[0]), "r"(a[1]), "r"(a[2]), "r"(a[3]), \
                   "r"(b[0]), "r"(b[1]))

#define BNAPP(v, s, h) { v = fmaf(v, s, h); v = (v > 0.f) ? v : expm1f(v); }

template<bool BN>
__global__ __launch_bounds__(256)
void gemm_tc(const float* __restrict__ A, const float* __restrict__ W,
             float* __restrict__ C, int M, int Nout, int K,
             const float* __restrict__ scp, const float* __restrict__ shp) {
    __shared__ unsigned int As[2][128 * SMP];
    __shared__ unsigned int Bs[2][128 * SMP];

    const int tid = threadIdx.x;
    const int m0 = blockIdx.y * 128;
    const int n0 = blockIdx.x * 128;
    const int lr = tid >> 1;
    const int lk = (tid & 1) * 8;
    const int lane = tid & 31;
    const int warp = tid >> 5;
    const int wm = (warp & 3) * 32;
    const int wn = (warp >> 2) * 64;
    const int qr = lane >> 2;
    const int qc = lane & 3;

    float acc[2][8][4];
#pragma unroll
    for (int mt = 0; mt < 2; mt++)
#pragma unroll
        for (int nt = 0; nt < 8; nt++)
#pragma unroll
            for (int i = 0; i < 4; i++) acc[mt][nt][i] = 0.0f;

    const int nch = K >> 4;
    float4 av0, av1, bv0, bv1;
    const float4 z4 = make_float4(0.f, 0.f, 0.f, 0.f);

#define LOADG(ch) { \
        int kb = ((ch) << 4) + lk; \
        int ar = m0 + lr; \
        if (ar < M) { \
            const float* ap = A + (size_t)ar * K + kb; \
            av0 = *(const float4*)ap; av1 = *(const float4*)(ap + 4); \
        } else { av0 = z4; av1 = z4; } \
        if (BN) { \
            float4 s0 = *(const float4*)&scp[kb]; \
            float4 s1 = *(const float4*)&scp[kb + 4]; \
            float4 h0 = *(const float4*)&shp[kb]; \
            float4 h1 = *(const float4*)&shp[kb + 4]; \
            BNAPP(av0.x, s0.x, h0.x); BNAPP(av0.y, s0.y, h0.y); \
            BNAPP(av0.z, s0.z, h0.z); BNAPP(av0.w, s0.w, h0.w); \
            BNAPP(av1.x, s1.x, h1.x); BNAPP(av1.y, s1.y, h1.y); \
            BNAPP(av1.z, s1.z, h1.z); BNAPP(av1.w, s1.w, h1.w); \
        } \
        int br = n0 + lr; \
        if (br < Nout) { \
            const float* bp = W + (size_t)br * K + kb; \
            bv0 = *(const float4*)bp; bv1 = *(const float4*)(bp + 4); \
        } else { bv0 = z4; bv1 = z4; } \
    }

#define STORES(bufi) { \
        uint4 ua0, ua1, ub0, ub1; \
        CVT_TF32(ua0.x, av0.x); CVT_TF32(ua0.y, av0.y); CVT_TF32(ua0.z, av0.z); CVT_TF32(ua0.w, av0.w); \
        CVT_TF32(ua1.x, av1.x); CVT_TF32(ua1.y, av1.y); CVT_TF32(ua1.z, av1.z); CVT_TF32(ua1.w, av1.w); \
        CVT_TF32(ub0.x, bv0.x); CVT_TF32(ub0.y, bv0.y); CVT_TF32(ub0.z, bv0.z); CVT_TF32(ub0.w, bv0.w); \
        CVT_TF32(ub1.x, bv1.x); CVT_TF32(ub1.y, bv1.y); CVT_TF32(ub1.z, bv1.z); CVT_TF32(ub1.w, bv1.w); \
        *(uint4*)&As[bufi][lr * SMP + lk]     = ua0; \
        *(uint4*)&As[bufi][lr * SMP + lk + 4] = ua1; \
        *(uint4*)&Bs[bufi][lr * SMP + lk]     = ub0; \
        *(uint4*)&Bs[bufi][lr * SMP + lk + 4] = ub1; \
    }

    LOADG(0);
    STORES(0);
    __syncthreads();

    int buf = 0;
    for (int ch = 0; ch < nch; ch++) {
        if (ch + 1 < nch) LOADG(ch + 1);
#pragma unroll
        for (int kk = 0; kk < 2; kk++) {
            unsigned int af[2][4], bfr[8][2];
            const int kq = kk * 8 + qc;
#pragma unroll
            for (int mt = 0; mt < 2; mt++) {
                int r = wm + mt * 16 + qr;
                af[mt][0] = As[buf][r * SMP + kq];
                af[mt][1] = As[buf][(r + 8) * SMP + kq];
                af[mt][2] = As[buf][r * SMP + kq + 4];
                af[mt][3] = As[buf][(r + 8) * SMP + kq + 4];
            }
#pragma unroll
            for (int nt = 0; nt < 8; nt++) {
                int n = wn + nt * 8 + qr;
                bfr[nt][0] = Bs[buf][n * SMP + kq];
                bfr[nt][1] = Bs[buf][n * SMP + kq + 4];
            }
#pragma unroll
            for (int mt = 0; mt < 2; mt++)
#pragma unroll
                for (int nt = 0; nt < 8; nt++)
                    MMA_TF32(acc[mt][nt], af[mt], bfr[nt]);
        }
        if (ch + 1 < nch) STORES(buf ^ 1);
        __syncthreads();
        buf ^= 1;
    }

#pragma unroll
    for (int mt = 0; mt < 2; mt++) {
        int r0 = m0 + wm + mt * 16 + qr;
        int r1 = r0 + 8;
#pragma unroll
        for (int nt = 0; nt < 8; nt++) {
            int cc = n0 + wn + nt * 8 + qc * 2;
            if (cc < Nout) {
                if (r0 < M)
                    *(float2*)&C[(size_t)r0 * Nout + cc] =
                        make_float2(acc[mt][nt][0], acc[mt][nt][1]);
                if (r1 < M)
                    *(float2*)&C[(size_t)r1 * Nout + cc] =
                        make_float2(acc[mt][nt][2], acc[mt][nt][3]);
            }
        }
    }
#undef LOADG
#undef STORES
}

// ---------------- SAGE aggregation + fused BN stats: grid-stride warps ---------
__global__ void sage_agg_stats(const int* __restrict__ rowptr, const int* __restrict__ csrc,
                               const float* __restrict__ yC, const float* __restrict__ bias,
                               float* __restrict__ pre, float* gsum, float* gss) {
    int lane = threadIdx.x & 31;
    int w0 = (blockIdx.x * blockDim.x + threadIdx.x) >> 5;
    int nwarps = (gridDim.x * blockDim.x) >> 5;
    float4 st = make_float4(0.f, 0.f, 0.f, 0.f);
    float4 sq = make_float4(0.f, 0.f, 0.f, 0.f);
    float4 b = *(const float4*)&bias[lane * 4];
    for (int w = w0; w < NN; w += nwarps) {
        int beg = rowptr[w], end = rowptr[w + 1];
        float4 acc = make_float4(0.f, 0.f, 0.f, 0.f);
        for (int p = beg; p < end; p++) {
            int s = csrc[p];
            float4 v = *(const float4*)&yC[(size_t)s * 256 + lane * 4];
            acc.x += v.x; acc.y += v.y; acc.z += v.z; acc.w += v.w;
        }
        float inv = 1.0f / fmaxf((float)(end - beg), 1.0f);
        float4 r = *(const float4*)&yC[(size_t)w * 256 + 128 + lane * 4];
        float4 o;
        o.x = acc.x * inv + b.x + r.x;
        o.y = acc.y * inv + b.y + r.y;
        o.z = acc.z * inv + b.z + r.z;
        o.w = acc.w * inv + b.w + r.w;
        *(float4*)&pre[(size_t)w * HID + lane * 4] = o;
        st.x += o.x; st.y += o.y; st.z += o.z; st.w += o.w;
        sq.x += o.x * o.x; sq.y += o.y * o.y; sq.z += o.z * o.z; sq.w += o.w * o.w;
    }
    atomicAdd(&gsum[lane * 4 + 0], st.x); atomicAdd(&gsum[lane * 4 + 1], st.y);
    atomicAdd(&gsum[lane * 4 + 2], st.z); atomicAdd(&gsum[lane * 4 + 3], st.w);
    atomicAdd(&gss[lane * 4 + 0], sq.x);  atomicAdd(&gss[lane * 4 + 1], sq.y);
    atomicAdd(&gss[lane * 4 + 2], sq.z);  atomicAdd(&gss[lane * 4 + 3], sq.w);
}

// ---------------- BN finalize: stats -> scale/shift ----------------
__global__ void finalize_bn(const float* __restrict__ gsum, const float* __restrict__ gss,
                            const float* __restrict__ gamma, const float* __restrict__ beta,
                            int N, float* sc, float* sh) {
    int c = threadIdx.x;
    float invN = 1.0f / (float)N;
    float mean = gsum[c] * invN;
    float var  = gss[c] * invN - mean * mean;
    float s = gamma[c] * rsqrtf(var + 1e-5f);
    sc[c] = s;
    sh[c] = beta[c] - mean * s;
}

// ---------------- low-rank attn precompute (8 blocks) ----------------
// block b = h*2+which; va[k*8 + 2h+which] = sum_d Wg[(h*128+d)*128+k] * a[h*128+d]
__global__ void attn_lowrank(const float* __restrict__ Wg, const float* __restrict__ a_s,
                             const float* __restrict__ a_d, float* __restrict__ va) {
    int k = threadIdx.x;
    int h = blockIdx.x >> 1;
    int which = blockIdx.x & 1;
    const float* a = which ? a_d : a_s;
    float acc = 0.f;
    for (int d = 0; d < HID; d++)
        acc += Wg[(size_t)(h * HID + d) * HID + k] * a[h * HID + d];
    va[k * 8 + 2 * h + which] = acc;
}

// ---------------- attn coefs from pre1 with fused BN+ELU: warp per node --------
__global__ void attn_coef_lr(const float* __restrict__ pre1, const float* __restrict__ va,
                             const float* __restrict__ sc, const float* __restrict__ sh,
                             float* asrc, float* adst, int N) {
    __shared__ float sva[HID * 8];
    __shared__ float ssc[HID], ssh[HID];
    int t = threadIdx.x;
    for (int i = t; i < HID * 8; i += blockDim.x) sva[i] = va[i];
    if (t < HID) { ssc[t] = sc[t]; ssh[t] = sh[t]; }
    __syncthreads();
    int w = (blockIdx.x * blockDim.x + t) >> 5;
    int lane = t & 31;
    if (w >= N) return;
    float4 v = *(const float4*)&pre1[(size_t)w * HID + lane * 4];
    int k0 = lane * 4;
    BNAPP(v.x, ssc[k0 + 0], ssh[k0 + 0]);
    BNAPP(v.y, ssc[k0 + 1], ssh[k0 + 1]);
    BNAPP(v.z, ssc[k0 + 2], ssh[k0 + 2]);
    BNAPP(v.w, ssc[k0 + 3], ssh[k0 + 3]);
    float acc[8];
#pragma unroll
    for (int j = 0; j < 8; j++) {
        acc[j] = v.x * sva[(k0 + 0) * 8 + j]
               + v.y * sva[(k0 + 1) * 8 + j]
               + v.z * sva[(k0 + 2) * 8 + j]
               + v.w * sva[(k0 + 3) * 8 + j];
    }
#pragma unroll
    for (int o = 16; o; o >>= 1)
#pragma unroll
        for (int j = 0; j < 8; j++)
            acc[j] += __shfl_xor_sync(0xffffffffu, acc[j], o);
    if (lane < 4) asrc[w * 4 + lane] = acc[2 * lane];
    else if (lane < 8) { int h = lane - 4; adst[w * 4 + h] = acc[2 * h + 1]; }
}

// ---------------- GAT fused + stats: persistent blocks (128 thr) ----------------
__global__ __launch_bounds__(128)
void gat_fused_stats(const int* __restrict__ rowptr, const int* __restrict__ csrc,
                     const float* __restrict__ asrc, const float* __restrict__ adst,
                     const float* __restrict__ xh, const float* __restrict__ gbias,
                     float* __restrict__ pre, float* gsum, float* gss) {
    __shared__ float s_mx[4], s_den[4], s_self[4];
    __shared__ float s_ex[GCAP * 4];
    int tid = threadIdx.x;
    int c = tid;
    int h = c >> 5;
    float4 bgb = *(const float4*)&gbias[c * 4];
    float4 st = make_float4(0.f, 0.f, 0.f, 0.f);
    float4 sq = make_float4(0.f, 0.f, 0.f, 0.f);

    for (int i = blockIdx.x; i < NN; i += gridDim.x) {
        int beg = rowptr[i], end = rowptr[i + 1];
        int deg = end - beg;

        if (tid < 4) {
            int hh = tid;
            float ad = adst[i * 4 + hh];
            float vs = asrc[i * 4 + hh] + ad;
            vs = (vs > 0.f) ? vs : 0.2f * vs;
            float mx = vs;
            for (int p = beg; p < end; p++) {
                float v = asrc[csrc[p] * 4 + hh] + ad;
                v = (v > 0.f) ? v : 0.2f * v;
                mx = fmaxf(mx, v);
            }
            float den = expf(vs - mx);
            s_self[hh] = den;
            for (int e = 0; e < deg; e++) {
                float v = asrc[csrc[beg + e] * 4 + hh] + ad;
                v = (v > 0.f) ? v : 0.2f * v;
                float ex = expf(v - mx);
                if (e < GCAP) s_ex[e * 4 + hh] = ex;
                den += ex;
            }
            s_mx[hh] = mx;
            s_den[hh] = den;
        }
        __syncthreads();

        float invden = 1.0f / s_den[h];
        float mx = s_mx[h];
        float ad = adst[i * 4 + h];

        float al = s_self[h] * invden;
        float4 v = *(const float4*)&xh[(size_t)i * H4 + c * 4];
        float4 acc;
        acc.x = al * v.x; acc.y = al * v.y; acc.z = al * v.z; acc.w = al * v.w;

        for (int e = 0; e < deg; e++) {
            int s = csrc[beg + e];
            float ex;
            if (e < GCAP) ex = s_ex[e * 4 + h];
            else {
                float lv = asrc[s * 4 + h] + ad;
                lv = (lv > 0.f) ? lv : 0.2f * lv;
                ex = expf(lv - mx);
            }
            float a = ex * invden;
            float4 u = *(const float4*)&xh[(size_t)s * H4 + c * 4];
            acc.x += a * u.x; acc.y += a * u.y; acc.z += a * u.z; acc.w += a * u.w;
        }
        acc.x += bgb.x; acc.y += bgb.y; acc.z += bgb.z; acc.w += bgb.w;
        *(float4*)&pre[(size_t)i * H4 + c * 4] = acc;
        st.x += acc.x; st.y += acc.y; st.z += acc.z; st.w += acc.w;
        sq.x += acc.x * acc.x; sq.y += acc.y * acc.y;
        sq.z += acc.z * acc.z; sq.w += acc.w * acc.w;
        __syncthreads();   // protect s_ex/s_mx before next iteration
    }
    atomicAdd(&gsum[c * 4 + 0], st.x); atomicAdd(&gsum[c * 4 + 1], st.y);
    atomicAdd(&gsum[c * 4 + 2], st.z); atomicAdd(&gsum[c * 4 + 3], st.w);
    atomicAdd(&gss[c * 4 + 0], sq.x);  atomicAdd(&gss[c * 4 + 1], sq.y);
    atomicAdd(&gss[c * 4 + 2], sq.z);  atomicAdd(&gss[c * 4 + 3], sq.w);
}

// ---------------- bias-add + BN stats (FC1 output) ----------------
__global__ void bias_stats(const float* __restrict__ in, const float* __restrict__ bias,
                           float* pre, float* gsum, float* gss, int N, int C) {
    int c = threadIdx.x;
    float bc = bias[c];
    float s = 0.f, ss = 0.f;
    for (int r = blockIdx.x; r < N; r += gridDim.x) {
        float v = in[(size_t)r * C + c] + bc;
        pre[(size_t)r * C + c] = v;
        s += v; ss += v * v;
    }
    atomicAdd(&gsum[c], s);
    atomicAdd(&gss[c], ss);
}

// ---------------- FC2 with fused BN+ELU: [N,64] -> [N,2] ----------------
__global__ void fc2_bn(const float* __restrict__ f1p,
                       const float* __restrict__ sc, const float* __restrict__ sh,
                       const float* __restrict__ W, const float* __restrict__ b,
                       float* out, int N) {
    __shared__ float sW[2 * FCH], ssc[FCH], ssh[FCH];
    int t = threadIdx.x;
    if (t < 2 * FCH) sW[t] = W[t];
    if (t < FCH) { ssc[t] = sc[t]; ssh[t] = sh[t]; }
    __syncthreads();
    int n = blockIdx.x * blockDim.x + t;
    if (n >= N) return;
    float a0 = b[0], a1 = b[1];
#pragma unroll
    for (int k = 0; k < FCH; k++) {
        float f = f1p[(size_t)n * FCH + k];
        BNAPP(f, ssc[k], ssh[k]);
        a0 += f * sW[k];
        a1 += f * sW[FCH + k];
    }
    out[n * 2 + 0] = a0;
    out[n * 2 + 1] = a1;
}

// ---------------- host launcher ----------------
static inline void gemm(const float* A, const float* W, float* C, int M, int Nout, int K) {
    dim3 grid((Nout + 127) / 128, (M + 127) / 128);
    gemm_tc<false><<<grid, 256>>>(A, W, C, M, Nout, K, nullptr, nullptr);
}
static inline void gemm_bn(const float* A, const float* W, float* C, int M, int Nout, int K,
                           const float* sc, const float* sh) {
    dim3 grid((Nout + 127) / 128, (M + 127) / 128);
    gemm_tc<true><<<grid, 256>>>(A, W, C, M, Nout, K, sc, sh);
}
static inline void fill(float* p, float v, long n) {
    long blocks = (n + 255) / 256;
    if (blocks > 131072) blocks = 131072;
    fillk<<<(int)blocks, 256>>>(p, v, n);
}

extern "C" void kernel_launch(void* const* d_in, const int* in_sizes, int n_in,
                              void* d_out, int out_size) {
    const float* x     = (const float*)d_in[0];
    const int*   ei    = (const int*)d_in[1];
    const int*   src   = ei;
    const int*   dst   = ei + EE;
    const float* W1l   = (const float*)d_in[2];
    const float* b1    = (const float*)d_in[3];
    const float* W1r   = (const float*)d_in[4];
    const float* g1    = (const float*)d_in[5];
    const float* be1   = (const float*)d_in[6];
    const float* Wg    = (const float*)d_in[7];
    const float* a_src = (const float*)d_in[8];
    const float* a_dst = (const float*)d_in[9];
    const float* gbias = (const float*)d_in[10];
    const float* g2    = (const float*)d_in[11];
    const float* be2   = (const float*)d_in[12];
    const float* W2l   = (const float*)d_in[13];
    const float* b2    = (const float*)d_in[14];
    const float* W2r   = (const float*)d_in[15];
    const float* g3    = (const float*)d_in[16];
    const float* be3   = (const float*)d_in[17];
    const float* Wf1   = (const float*)d_in[18];
    const float* bf1   = (const float*)d_in[19];
    const float* g4    = (const float*)d_in[20];
    const float* be4   = (const float*)d_in[21];
    const float* Wf2   = (const float*)d_in[22];
    const float* bf2   = (const float*)d_in[23];
    float* outp = (float*)d_out;

#define SYM(T, p, s) T* p; cudaGetSymbolAddress((void**)&p, s)
    SYM(float, yC, g_yC);
    SYM(float, pre1, g_pre1); SYM(float, xh, g_xh);
    SYM(float, asrc, g_asrc); SYM(float, adst, g_adst);
    SYM(float, pre2, g_pre2);
    SYM(float, y2C, g_y2C);
    SYM(float, pre3, g_pre3);
    SYM(float, f1p, g_f1p);
    SYM(float, stats, g_stats); SYM(float, scsh, g_scsh);
    SYM(float, wcat1, g_wcat1); SYM(float, wcat2, g_wcat2);
    SYM(float, va, g_va);
    SYM(int, rowptr, g_rowptr); SYM(int, cnt, g_cnt);
    SYM(int, cnt2, g_cnt2); SYM(int, csrc, g_csrc);
    SYM(int, bsum, g_bsum); SYM(int, boff, g_boff);
#undef SYM
    float* gsum = stats;
    float* gss  = stats + 512;
    float* sc1 = scsh;        float* sh1 = scsh + 128;
    float* sc2 = scsh + 256;  float* sh2 = scsh + 768;
    float* sc3 = scsh + 1280; float* sh3 = scsh + 1408;
    float* sc4 = scsh + 1536; float* sh4 = scsh + 1600;

    // weight concat (D2D async; graph-capturable)
    cudaMemcpyAsync(wcat1,             W1l, (size_t)HID * INC * 4, cudaMemcpyDeviceToDevice);
    cudaMemcpyAsync(wcat1 + HID * INC, W1r, (size_t)HID * INC * 4, cudaMemcpyDeviceToDevice);
    cudaMemcpyAsync(wcat2,             W2l, (size_t)HID * H4 * 4, cudaMemcpyDeviceToDevice);
    cudaMemcpyAsync(wcat2 + HID * H4,  W2r, (size_t)HID * H4 * 4, cudaMemcpyDeviceToDevice);

    // ===== CSR build (decoupled scan) =====
    fill((float*)cnt, 0.f, NN);
    fill((float*)cnt2, 0.f, NN);
    count_kernel<<<(EE + 255) / 256, 256>>>(dst, cnt, EE);
    scan_part<<<NB, 256>>>(cnt, bsum);
    scan_tops<<<1, 256>>>(bsum, boff, rowptr);
    scan_expand<<<NB, 256>>>(cnt, boff, rowptr);
    scatter_kernel<<<(EE + 255) / 256, 256>>>(src, dst, rowptr, cnt2, csrc, EE);

    // attn low-rank precompute (8 blocks; independent of h1)
    attn_lowrank<<<8, 128>>>(Wg, a_src, a_dst, va);

    // ===== SAGE layer 1 =====
    fill(stats, 0.f, 1024);
    gemm(x, wcat1, yC, NN, 256, INC);
    sage_agg_stats<<<512, 256>>>(rowptr, csrc, yC, b1, pre1, gsum, gss);
    finalize_bn<<<1, HID>>>(gsum, gss, g1, be1, NN, sc1, sh1);

    // ===== GAT layer (BN+ELU fused into consumers of pre1) =====
    gemm_bn(pre1, Wg, xh, NN, H4, HID, sc1, sh1);
    attn_coef_lr<<<(NN * 32 + 255) / 256, 256>>>(pre1, va, sc1, sh1, asrc, adst, NN);
    fill(stats, 0.f, 1024);
    gat_fused_stats<<<2048, 128>>>(rowptr, csrc, asrc, adst, xh, gbias, pre2, gsum, gss);
    finalize_bn<<<1, H4>>>(gsum, gss, g2, be2, NN, sc2, sh2);

    // ===== SAGE layer 2 (BN+ELU on pre2 fused into GEMM load) =====
    gemm_bn(pre2, wcat2, y2C, NN, 256, H4, sc2, sh2);
    fill(stats, 0.f, 1024);
    sage_agg_stats<<<512, 256>>>(rowptr, csrc, y2C, b2, pre3, gsum, gss);
    finalize_bn<<<1, HID>>>(gsum, gss, g3, be3, NN, sc3, sh3);

    // ===== FC head (BN+ELU on pre3 fused into FC1 GEMM load) =====
    gemm_bn(pre3, Wf1, f1p, NN, FCH, HID, sc3, sh3);
    fill(stats, 0.f, 1024);
    bias_stats<<<1024, FCH>>>(f1p, bf1, f1p, gsum, gss, NN, FCH);
    finalize_bn<<<1, FCH>>>(gsum, gss, g4, be4, NN, sc4, sh4);
    fc2_bn<<<(NN + 127) / 128, 128>>>(f1p, sc4, sh4, Wf2, bf2, outp, NN);
}

// round 10
// speedup vs baseline: 1.3520x; 1.3520x over previous
#include <cuda_runtime.h>
#include <cuda_bf16.h>
#include <math.h>

#define NN   50000
#define EE   400000
#define INC  256
#define HID  128
#define H4   512
#define FCH  64
#define OUTC 2
#define GCAP 256   // smem exp cache per head in gat_fused
#define NB   ((NN + 255) / 256)   // scan tiles = 196

// ---------------- scratch (device globals; no allocation allowed) ----------------
__device__ float g_yC  [NN * 256];   // [lin_l | lin_r] concat, SAGE1
__device__ float g_pre1[NN * HID];
__device__ float g_h1  [NN * HID];
__device__ float g_xh  [NN * H4];
__device__ float g_asrc[NN * 4];
__device__ float g_adst[NN * 4];
__device__ float g_pre2[NN * H4];
__device__ float g_h2  [NN * H4];
__device__ float g_y2C [NN * 256];   // [lin_l | lin_r] concat, SAGE2
__device__ float g_pre3[NN * HID];
__device__ float g_h3  [NN * HID];
__device__ float g_f1p [NN * FCH];
__device__ float g_f1  [NN * FCH];
__device__ float g_stats[1024];      // [0:512) sum, [512:1024) sumsq
__device__ float g_wcat1[256 * INC];
__device__ float g_wcat2[256 * H4];
__device__ int   g_rowptr[NN + 1];
__device__ int   g_cnt [NN];
__device__ int   g_cnt2[NN];
__device__ int   g_bsum[NB];
__device__ int   g_boff[NB];
__device__ int   g_csrc[EE];         // CSR: src node per slot, grouped by dst

// ---------------- generic fill ----------------
__global__ void fillk(float* p, float v, long n) {
    long i = (long)blockIdx.x * blockDim.x + threadIdx.x;
    long stride = (long)gridDim.x * blockDim.x;
    for (; i < n; i += stride) p[i] = v;
}

// ---------------- CSR build ----------------
__global__ void count_kernel(const int* __restrict__ dst, int* cnt, int E) {
    int e = blockIdx.x * blockDim.x + threadIdx.x;
    if (e < E) atomicAdd(&cnt[dst[e]], 1);
}

// decoupled scan, stage 1: per-tile (256) sums
__global__ void scan_part(const int* __restrict__ cnt, int* bsum) {
    __shared__ int s[256];
    int t = threadIdx.x;
    int i = blockIdx.x * 256 + t;
    int v = (i < NN) ? cnt[i] : 0;
    s[t] = v;
    __syncthreads();
    for (int off = 128; off; off >>= 1) {
        if (t < off) s[t] += s[t + off];
        __syncthreads();
    }
    if (t == 0) bsum[blockIdx.x] = s[0];
}

// stage 2: exclusive scan of NB tile sums (single block)
__global__ void scan_tops(const int* __restrict__ bsum, int* boff, int* rowptr) {
    __shared__ int s[256];
    int t = threadIdx.x;
    int v = (t < NB) ? bsum[t] : 0;
    s[t] = v;
    __syncthreads();
#pragma unroll
    for (int off = 1; off < 256; off <<= 1) {
        int u = (t >= off) ? s[t - off] : 0;
        __syncthreads();
        s[t] += u;
        __syncthreads();
    }
    if (t < NB) boff[t] = s[t] - v;        // exclusive
    if (t == 255) rowptr[NN] = s[255];     // total
}

// stage 3: per-tile inclusive scan + offset -> exclusive rowptr
__global__ void scan_expand(const int* __restrict__ cnt, const int* __restrict__ boff,
                            int* rowptr) {
    __shared__ int s[256];
    int t = threadIdx.x;
    int i = blockIdx.x * 256 + t;
    int v = (i < NN) ? cnt[i] : 0;
    s[t] = v;
    __syncthreads();
#pragma unroll
    for (int off = 1; off < 256; off <<= 1) {
        int u = (t >= off) ? s[t - off] : 0;
        __syncthreads();
        s[t] += u;
        __syncthreads();
    }
    if (i < NN) rowptr[i] = boff[blockIdx.x] + s[t] - v;
}

__global__ void scatter_kernel(const int* __restrict__ src, const int* __restrict__ dst,
                               const int* __restrict__ rowptr, int* cnt2, int* csrc, int E) {
    int e = blockIdx.x * blockDim.x + threadIdx.x;
    if (e >= E) return;
    int d = dst[e];
    int pos = rowptr[d] + atomicAdd(&cnt2[d], 1);
    csrc[pos] = src[e];
}

// =====================================================================
// Tensor-core GEMM: C[m,n] = sum_k A[m,k] * W[n,k]   (tf32 HMMA)
// =====================================================================
#define SMP 20

#define CVT_TF32(u, f) asm("cvt.rna.tf32.f32 %0, %1;" : "=r"(u) : "f"(f))

#define MMA_TF32(c, a, b) \
    asm volatile("mma.sync.aligned.m16n8k8.row.col.f32.tf32.tf32.f32 " \
                 "{%0,%1,%2,%3}, {%4,%5,%6,%7}, {%8,%9}, {%0,%1,%2,%3};" \
                 : "+f"(c[0]), "+f"(c[1]), "+f"(c[2]), "+f"(c[3]) \
                 : "r"(a[0]), "r"(a[1]), "r"(a[2]), "r"(a[3]), \
                   "r"(b[0]), "r"(b[1]))

__global__ __launch_bounds__(256)
void gemm_tc(const float* __restrict__ A, const float* __restrict__ W,
             float* __restrict__ C, int M, int Nout, int K) {
    __shared__ unsigned int As[2][128 * SMP];
    __shared__ unsigned int Bs[2][128 * SMP];

    const int tid = threadIdx.x;
    const int m0 = blockIdx.y * 128;
    const int n0 = blockIdx.x * 128;
    const int lr = tid >> 1;
    const int lk = (tid & 1) * 8;
    const int lane = tid & 31;
    const int warp = tid >> 5;
    const int wm = (warp & 3) * 32;
    const int wn = (warp >> 2) * 64;
    const int qr = lane >> 2;
    const int qc = lane & 3;

    float acc[2][8][4];
#pragma unroll
    for (int mt = 0; mt < 2; mt++)
#pragma unroll
        for (int nt = 0; nt < 8; nt++)
#pragma unroll
            for (int i = 0; i < 4; i++) acc[mt][nt][i] = 0.0f;

    const int nch = K >> 4;
    float4 av0, av1, bv0, bv1;
    const float4 z4 = make_float4(0.f, 0.f, 0.f, 0.f);

#define LOADG(ch) { \
        int kb = ((ch) << 4) + lk; \
        int ar = m0 + lr; \
        if (ar < M) { \
            const float* ap = A + (size_t)ar * K + kb; \
            av0 = *(const float4*)ap; av1 = *(const float4*)(ap + 4); \
        } else { av0 = z4; av1 = z4; } \
        int br = n0 + lr; \
        if (br < Nout) { \
            const float* bp = W + (size_t)br * K + kb; \
            bv0 = *(const float4*)bp; bv1 = *(const float4*)(bp + 4); \
        } else { bv0 = z4; bv1 = z4; } \
    }

#define STORES(bufi) { \
        uint4 ua0, ua1, ub0, ub1; \
        CVT_TF32(ua0.x, av0.x); CVT_TF32(ua0.y, av0.y); CVT_TF32(ua0.z, av0.z); CVT_TF32(ua0.w, av0.w); \
        CVT_TF32(ua1.x, av1.x); CVT_TF32(ua1.y, av1.y); CVT_TF32(ua1.z, av1.z); CVT_TF32(ua1.w, av1.w); \
        CVT_TF32(ub0.x, bv0.x); CVT_TF32(ub0.y, bv0.y); CVT_TF32(ub0.z, bv0.z); CVT_TF32(ub0.w, bv0.w); \
        CVT_TF32(ub1.x, bv1.x); CVT_TF32(ub1.y, bv1.y); CVT_TF32(ub1.z, bv1.z); CVT_TF32(ub1.w, bv1.w); \
        *(uint4*)&As[bufi][lr * SMP + lk]     = ua0; \
        *(uint4*)&As[bufi][lr * SMP + lk + 4] = ua1; \
        *(uint4*)&Bs[bufi][lr * SMP + lk]     = ub0; \
        *(uint4*)&Bs[bufi][lr * SMP + lk + 4] = ub1; \
    }

    LOADG(0);
    STORES(0);
    __syncthreads();

    int buf = 0;
    for (int ch = 0; ch < nch; ch++) {
        if (ch + 1 < nch) LOADG(ch + 1);
#pragma unroll
        for (int kk = 0; kk < 2; kk++) {
            unsigned int af[2][4], bfr[8][2];
            const int kq = kk * 8 + qc;
#pragma unroll
            for (int mt = 0; mt < 2; mt++) {
                int r = wm + mt * 16 + qr;
                af[mt][0] = As[buf][r * SMP + kq];
                af[mt][1] = As[buf][(r + 8) * SMP + kq];
                af[mt][2] = As[buf][r * SMP + kq + 4];
                af[mt][3] = As[buf][(r + 8) * SMP + kq + 4];
            }
#pragma unroll
            for (int nt = 0; nt < 8; nt++) {
                int n = wn + nt * 8 + qr;
                bfr[nt][0] = Bs[buf][n * SMP + kq];
                bfr[nt][1] = Bs[buf][n * SMP + kq + 4];
            }
#pragma unroll
            for (int mt = 0; mt < 2; mt++)
#pragma unroll
                for (int nt = 0; nt < 8; nt++)
                    MMA_TF32(acc[mt][nt], af[mt], bfr[nt]);
        }
        if (ch + 1 < nch) STORES(buf ^ 1);
        __syncthreads();
        buf ^= 1;
    }

#pragma unroll
    for (int mt = 0; mt < 2; mt++) {
        int r0 = m0 + wm + mt * 16 + qr;
        int r1 = r0 + 8;
#pragma unroll
        for (int nt = 0; nt < 8; nt++) {
            int cc = n0 + wn + nt * 8 + qc * 2;
            if (cc < Nout) {
                if (r0 < M)
                    *(float2*)&C[(size_t)r0 * Nout + cc] =
                        make_float2(acc[mt][nt][0], acc[mt][nt][1]);
                if (r1 < M)
                    *(float2*)&C[(size_t)r1 * Nout + cc] =
                        make_float2(acc[mt][nt][2], acc[mt][nt][3]);
            }
        }
    }
#undef LOADG
#undef STORES
}

// ---------------- SAGE fused aggregation: warp per node (CSR gather) ----------
__global__ void sage_agg(const int* __restrict__ rowptr, const int* __restrict__ csrc,
                         const float* __restrict__ yC, const float* __restrict__ bias,
                         float* __restrict__ pre) {
    int w = (blockIdx.x * blockDim.x + threadIdx.x) >> 5;
    int lane = threadIdx.x & 31;
    if (w >= NN) return;
    int beg = rowptr[w], end = rowptr[w + 1];
    float4 acc = make_float4(0.f, 0.f, 0.f, 0.f);
    for (int p = beg; p < end; p++) {
        int s = csrc[p];
        float4 v = *(const float4*)&yC[(size_t)s * 256 + lane * 4];
        acc.x += v.x; acc.y += v.y; acc.z += v.z; acc.w += v.w;
    }
    float inv = 1.0f / fmaxf((float)(end - beg), 1.0f);
    float4 r = *(const float4*)&yC[(size_t)w * 256 + 128 + lane * 4];
    float4 b = *(const float4*)&bias[lane * 4];
    float4 o;
    o.x = acc.x * inv + b.x + r.x;
    o.y = acc.y * inv + b.y + r.y;
    o.z = acc.z * inv + b.z + r.z;
    o.w = acc.w * inv + b.w + r.w;
    *(float4*)&pre[(size_t)w * HID + lane * 4] = o;
}

// ---------------- GAT attention coefficients: warp per (n,h) ----------------
__global__ void attn_coef(const float* __restrict__ xh, const float* __restrict__ a_s,
                          const float* __restrict__ a_d, float* asrc, float* adst, int N) {
    int gw = (blockIdx.x * blockDim.x + threadIdx.x) >> 5;
    int lane = threadIdx.x & 31;
    if (gw >= N * 4) return;
    int n = gw >> 2, h = gw & 3;
    float4 v = *(const float4*)&xh[(size_t)n * H4 + h * HID + lane * 4];
    float4 s = *(const float4*)&a_s[h * HID + lane * 4];
    float4 d = *(const float4*)&a_d[h * HID + lane * 4];
    float accs = v.x * s.x + v.y * s.y + v.z * s.z + v.w * s.w;
    float accd = v.x * d.x + v.y * d.y + v.z * d.z + v.w * d.w;
#pragma unroll
    for (int o = 16; o; o >>= 1) {
        accs += __shfl_xor_sync(0xffffffffu, accs, o);
        accd += __shfl_xor_sync(0xffffffffu, accd, o);
    }
    if (lane == 0) { asrc[n * 4 + h] = accs; adst[n * 4 + h] = accd; }
}

// ---------------- GAT fused: block (128 thr) per node ----------------
__global__ __launch_bounds__(128)
void gat_fused(const int* __restrict__ rowptr, const int* __restrict__ csrc,
               const float* __restrict__ asrc, const float* __restrict__ adst,
               const float* __restrict__ xh, const float* __restrict__ gbias,
               float* __restrict__ pre) {
    __shared__ float s_mx[4], s_den[4], s_self[4];
    __shared__ float s_ex[GCAP * 4];
    int i = blockIdx.x;
    int tid = threadIdx.x;
    int beg = rowptr[i], end = rowptr[i + 1];
    int deg = end - beg;

    if (tid < 4) {
        int h = tid;
        float ad = adst[i * 4 + h];
        float vs = asrc[i * 4 + h] + ad;
        vs = (vs > 0.f) ? vs : 0.2f * vs;              // self-loop logit
        float mx = vs;
        for (int p = beg; p < end; p++) {
            float v = asrc[csrc[p] * 4 + h] + ad;
            v = (v > 0.f) ? v : 0.2f * v;
            mx = fmaxf(mx, v);
        }
        float den = expf(vs - mx);
        s_self[h] = den;
        for (int e = 0; e < deg; e++) {
            float v = asrc[csrc[beg + e] * 4 + h] + ad;
            v = (v > 0.f) ? v : 0.2f * v;
            float ex = expf(v - mx);
            if (e < GCAP) s_ex[e * 4 + h] = ex;
            den += ex;
        }
        s_mx[h] = mx;
        s_den[h] = den;
    }
    __syncthreads();

    int c = tid;              // float4 channel index 0..127 over 512 channels
    int h = c >> 5;
    float invden = 1.0f / s_den[h];
    float mx = s_mx[h];
    float ad = adst[i * 4 + h];

    float al = s_self[h] * invden;
    float4 v = *(const float4*)&xh[(size_t)i * H4 + c * 4];
    float4 acc;
    acc.x = al * v.x; acc.y = al * v.y; acc.z = al * v.z; acc.w = al * v.w;

    for (int e = 0; e < deg; e++) {
        int s = csrc[beg + e];
        float ex;
        if (e < GCAP) ex = s_ex[e * 4 + h];
        else {
            float lv = asrc[s * 4 + h] + ad;
            lv = (lv > 0.f) ? lv : 0.2f * lv;
            ex = expf(lv - mx);
        }
        float a = ex * invden;
        float4 u = *(const float4*)&xh[(size_t)s * H4 + c * 4];
        acc.x += a * u.x; acc.y += a * u.y; acc.z += a * u.z; acc.w += a * u.w;
    }
    float4 b = *(const float4*)&gbias[c * 4];
    acc.x += b.x; acc.y += b.y; acc.z += b.z; acc.w += b.w;
    *(float4*)&pre[(size_t)i * H4 + c * 4] = acc;
}

// ---------------- BN stats ----------------
__global__ void stats_only(const float* __restrict__ pre,
                           float* gsum, float* gss, int N, int C) {
    int c = threadIdx.x;
    float s = 0.f, ss = 0.f;
    for (int r = blockIdx.x; r < N; r += gridDim.x) {
        float v = pre[(size_t)r * C + c];
        s += v; ss += v * v;
    }
    atomicAdd(&gsum[c], s);
    atomicAdd(&gss[c], ss);
}

__global__ void bias_stats(const float* __restrict__ in, const float* __restrict__ bias,
                           float* pre, float* gsum, float* gss, int N, int C) {
    int c = threadIdx.x;
    float bc = bias[c];
    float s = 0.f, ss = 0.f;
    for (int r = blockIdx.x; r < N; r += gridDim.x) {
        float v = in[(size_t)r * C + c] + bc;
        pre[(size_t)r * C + c] = v;
        s += v; ss += v * v;
    }
    atomicAdd(&gsum[c], s);
    atomicAdd(&gss[c], ss);
}

__global__ void bn_elu(const float* __restrict__ pre, float* out,
                       const float* __restrict__ gsum, const float* __restrict__ gss,
                       const float* __restrict__ gamma, const float* __restrict__ beta,
                       int N, int C) {
    int c = threadIdx.x;
    const float invN = 1.0f / (float)N;
    float mean = gsum[c] * invN;
    float var  = gss[c] * invN - mean * mean;
    float sc = gamma[c] * rsqrtf(var + 1e-5f);
    float sh = beta[c] - mean * sc;
    for (int r = blockIdx.x; r < N; r += gridDim.x) {
        float v = pre[(size_t)r * C + c] * sc + sh;
        out[(size_t)r * C + c] = (v > 0.0f) ? v : expm1f(v);
    }
}

// ---------------- FC2: [N,64] -> [N,2] ----------------
__global__ void fc2_kernel(const float* __restrict__ f1, const float* __restrict__ W,
                           const float* __restrict__ b, float* out, int N) {
    int n = blockIdx.x * blockDim.x + threadIdx.x;
    if (n >= N) return;
    float a0 = b[0], a1 = b[1];
#pragma unroll
    for (int k = 0; k < FCH; k++) {
        float f = f1[(size_t)n * FCH + k];
        a0 += f * W[k];
        a1 += f * W[FCH + k];
    }
    out[n * 2 + 0] = a0;
    out[n * 2 + 1] = a1;
}

// ---------------- host launcher ----------------
static inline void gemm(const float* A, const float* W, float* C, int M, int Nout, int K) {
    dim3 grid((Nout + 127) / 128, (M + 127) / 128);
    gemm_tc<<<grid, 256>>>(A, W, C, M, Nout, K);
}
static inline void fill(float* p, float v, long n) {
    long blocks = (n + 255) / 256;
    if (blocks > 131072) blocks = 131072;
    fillk<<<(int)blocks, 256>>>(p, v, n);
}

extern "C" void kernel_launch(void* const* d_in, const int* in_sizes, int n_in,
                              void* d_out, int out_size) {
    const float* x     = (const float*)d_in[0];
    const int*   ei    = (const int*)d_in[1];
    const int*   src   = ei;
    const int*   dst   = ei + EE;
    const float* W1l   = (const float*)d_in[2];
    const float* b1    = (const float*)d_in[3];
    const float* W1r   = (const float*)d_in[4];
    const float* g1    = (const float*)d_in[5];
    const float* be1   = (const float*)d_in[6];
    const float* Wg    = (const float*)d_in[7];
    const float* a_src = (const float*)d_in[8];
    const float* a_dst = (const float*)d_in[9];
    const float* gbias = (const float*)d_in[10];
    const float* g2    = (const float*)d_in[11];
    const float* be2   = (const float*)d_in[12];
    const float* W2l   = (const float*)d_in[13];
    const float* b2    = (const float*)d_in[14];
    const float* W2r   = (const float*)d_in[15];
    const float* g3    = (const float*)d_in[16];
    const float* be3   = (const float*)d_in[17];
    const float* Wf1   = (const float*)d_in[18];
    const float* bf1   = (const float*)d_in[19];
    const float* g4    = (const float*)d_in[20];
    const float* be4   = (const float*)d_in[21];
    const float* Wf2   = (const float*)d_in[22];
    const float* bf2   = (const float*)d_in[23];
    float* outp = (float*)d_out;

#define SYM(T, p, s) T* p; cudaGetSymbolAddress((void**)&p, s)
    SYM(float, yC, g_yC);
    SYM(float, pre1, g_pre1); SYM(float, h1, g_h1); SYM(float, xh, g_xh);
    SYM(float, asrc, g_asrc); SYM(float, adst, g_adst);
    SYM(float, pre2, g_pre2); SYM(float, h2, g_h2);
    SYM(float, y2C, g_y2C);
    SYM(float, pre3, g_pre3); SYM(float, h3, g_h3);
    SYM(float, f1p, g_f1p); SYM(float, f1, g_f1);
    SYM(float, stats, g_stats);
    SYM(float, wcat1, g_wcat1); SYM(float, wcat2, g_wcat2);
    SYM(int, rowptr, g_rowptr); SYM(int, cnt, g_cnt);
    SYM(int, cnt2, g_cnt2); SYM(int, csrc, g_csrc);
    SYM(int, bsum, g_bsum); SYM(int, boff, g_boff);
#undef SYM
    float* gsum = stats;
    float* gss  = stats + 512;
    const int STAT_BLOCKS = 1024;

    // weight concat (D2D async; graph-capturable)
    cudaMemcpyAsync(wcat1,             W1l, (size_t)HID * INC * 4, cudaMemcpyDeviceToDevice);
    cudaMemcpyAsync(wcat1 + HID * INC, W1r, (size_t)HID * INC * 4, cudaMemcpyDeviceToDevice);
    cudaMemcpyAsync(wcat2,             W2l, (size_t)HID * H4 * 4, cudaMemcpyDeviceToDevice);
    cudaMemcpyAsync(wcat2 + HID * H4,  W2r, (size_t)HID * H4 * 4, cudaMemcpyDeviceToDevice);

    // ===== CSR build (decoupled scan) =====
    fill((float*)cnt, 0.f, NN);
    fill((float*)cnt2, 0.f, NN);
    count_kernel<<<(EE + 255) / 256, 256>>>(dst, cnt, EE);
    scan_part<<<NB, 256>>>(cnt, bsum);
    scan_tops<<<1, 256>>>(bsum, boff, rowptr);
    scan_expand<<<NB, 256>>>(cnt, boff, rowptr);
    scatter_kernel<<<(EE + 255) / 256, 256>>>(src, dst, rowptr, cnt2, csrc, EE);

    // ===== SAGE layer 1 =====
    gemm(x, wcat1, yC, NN, 256, INC);
    sage_agg<<<(NN * 32 + 255) / 256, 256>>>(rowptr, csrc, yC, b1, pre1);
    fill(stats, 0.f, 1024);
    stats_only<<<STAT_BLOCKS, HID>>>(pre1, gsum, gss, NN, HID);
    bn_elu<<<STAT_BLOCKS, HID>>>(pre1, h1, gsum, gss, g1, be1, NN, HID);

    // ===== GAT layer =====
    gemm(h1, Wg, xh, NN, H4, HID);
    attn_coef<<<(NN * 4 * 32 + 255) / 256, 256>>>(xh, a_src, a_dst, asrc, adst, NN);
    gat_fused<<<NN, 128>>>(rowptr, csrc, asrc, adst, xh, gbias, pre2);
    fill(stats, 0.f, 1024);
    stats_only<<<STAT_BLOCKS, H4>>>(pre2, gsum, gss, NN, H4);
    bn_elu<<<STAT_BLOCKS, H4>>>(pre2, h2, gsum, gss, g2, be2, NN, H4);

    // ===== SAGE layer 2 =====
    gemm(h2, wcat2, y2C, NN, 256, H4);
    sage_agg<<<(NN * 32 + 255) / 256, 256>>>(rowptr, csrc, y2C, b2, pre3);
    fill(stats, 0.f, 1024);
    stats_only<<<STAT_BLOCKS, HID>>>(pre3, gsum, gss, NN, HID);
    bn_elu<<<STAT_BLOCKS, HID>>>(pre3, h3, gsum, gss, g3, be3, NN, HID);

    // ===== FC head =====
    gemm(h3, Wf1, f1p, NN, FCH, HID);
    fill(stats, 0.f, 1024);
    bias_stats<<<STAT_BLOCKS, FCH>>>(f1p, bf1, f1p, gsum, gss, NN, FCH);
    bn_elu<<<STAT_BLOCKS, FCH>>>(f1p, f1, gsum, gss, g4, be4, NN, FCH);
    fc2_kernel<<<(NN + 255) / 256, 256>>>(f1, Wf2, bf2, outp, NN);
}